// round 1
// baseline (speedup 1.0000x reference)
#include <cuda_runtime.h>
#include <math.h>

#define B_   32
#define N_   512
#define C_   768
#define H_   12
#define D_   64
#define HID_ 3072
#define M_   (B_*N_)   // 16384 rows

// ---------------- scratch (device globals; no allocation allowed) ----------
__device__ float g_h1  [(size_t)M_ * C_];        // LN1 output
__device__ float g_qkv [(size_t)M_ * 3 * C_];    // QKV projection
__device__ float g_attn[(size_t)M_ * C_];        // attention output (pre-proj)
__device__ float g_x2  [(size_t)M_ * C_];        // 2*proj(attn)  (residual stream)
__device__ float g_ln2 [(size_t)M_ * C_];        // LN2 output
__device__ float g_fc1 [(size_t)M_ * HID_];      // FC1+GELU output

// ---------------- fused LayerNorm: one block per row, C=768=3*256 ----------
__global__ void __launch_bounds__(256) ln_kernel(const float* __restrict__ x,
                                                 const float* __restrict__ w,
                                                 const float* __restrict__ b,
                                                 float* __restrict__ out)
{
    __shared__ float red[8];
    const int row = blockIdx.x;
    const int t   = threadIdx.x;
    const float* xr = x + (size_t)row * C_;

    float v0 = xr[t], v1 = xr[t + 256], v2 = xr[t + 512];
    float s = v0 + v1 + v2;
    #pragma unroll
    for (int o = 16; o; o >>= 1) s += __shfl_xor_sync(0xffffffffu, s, o);
    if ((t & 31) == 0) red[t >> 5] = s;
    __syncthreads();
    float tot = red[0]+red[1]+red[2]+red[3]+red[4]+red[5]+red[6]+red[7];
    const float mu = tot * (1.0f / C_);

    float d0 = v0 - mu, d1 = v1 - mu, d2 = v2 - mu;
    float q = d0*d0 + d1*d1 + d2*d2;
    #pragma unroll
    for (int o = 16; o; o >>= 1) q += __shfl_xor_sync(0xffffffffu, q, o);
    __syncthreads();                       // everyone done reading red[]
    if ((t & 31) == 0) red[t >> 5] = q;
    __syncthreads();
    float var = (red[0]+red[1]+red[2]+red[3]+red[4]+red[5]+red[6]+red[7]) * (1.0f / C_);
    const float rstd = rsqrtf(var + 1e-5f);

    float* orow = out + (size_t)row * C_;
    orow[t]       = d0 * rstd * w[t]       + b[t];
    orow[t + 256] = d1 * rstd * w[t + 256] + b[t + 256];
    orow[t + 512] = d2 * rstd * w[t + 512] + b[t + 512];
}

// ---------------- GEMM: C[M,N] = A[M,K] @ W[N,K]^T  (+epilogue) ------------
// MODE 0: plain (no bias)        (QKV)
// MODE 1: 2*(acc+bias)           (proj -> residual stream x2)
// MODE 2: gelu_exact(acc+bias)   (FC1)
// MODE 3: acc+bias+res           (FC2 + residual)
// BM=BN=128, BK=16, 256 threads, 8x8 per-thread tile. All dims divide tiles.
template <int MODE>
__global__ void __launch_bounds__(256) gemm_kernel(const float* __restrict__ A,
                                                   const float* __restrict__ W,
                                                   const float* __restrict__ bias,
                                                   const float* __restrict__ res,
                                                   float* __restrict__ Cout,
                                                   int M, int Nn, int K)
{
    __shared__ float As[16][128];
    __shared__ float Bs[16][128];

    const int bm = blockIdx.y, bn = blockIdx.x;
    const int tid = threadIdx.x;
    const int tr = tid >> 4;          // 0..15 -> C rows tr*8..+8
    const int tc = tid & 15;          // 0..15 -> C cols tc*8..+8
    const int lr = tid >> 2;          // 0..63 load row
    const int lc = (tid & 3) * 4;     // 0,4,8,12 load col (k)

    const float* Ab = A + (size_t)bm * 128 * K;
    const float* Wb = W + (size_t)bn * 128 * K;

    float acc[8][8];
    #pragma unroll
    for (int i = 0; i < 8; i++)
        #pragma unroll
        for (int j = 0; j < 8; j++) acc[i][j] = 0.0f;

    for (int k0 = 0; k0 < K; k0 += 16) {
        float4 a0 = *(const float4*)(Ab + (size_t)lr        * K + k0 + lc);
        float4 a1 = *(const float4*)(Ab + (size_t)(lr + 64) * K + k0 + lc);
        float4 b0 = *(const float4*)(Wb + (size_t)lr        * K + k0 + lc);
        float4 b1 = *(const float4*)(Wb + (size_t)(lr + 64) * K + k0 + lc);
        __syncthreads();   // previous compute done before overwrite
        As[lc+0][lr] = a0.x; As[lc+1][lr] = a0.y; As[lc+2][lr] = a0.z; As[lc+3][lr] = a0.w;
        As[lc+0][lr+64] = a1.x; As[lc+1][lr+64] = a1.y; As[lc+2][lr+64] = a1.z; As[lc+3][lr+64] = a1.w;
        Bs[lc+0][lr] = b0.x; Bs[lc+1][lr] = b0.y; Bs[lc+2][lr] = b0.z; Bs[lc+3][lr] = b0.w;
        Bs[lc+0][lr+64] = b1.x; Bs[lc+1][lr+64] = b1.y; Bs[lc+2][lr+64] = b1.z; Bs[lc+3][lr+64] = b1.w;
        __syncthreads();

        #pragma unroll
        for (int k = 0; k < 16; k++) {
            float4 m0 = *(const float4*)&As[k][tr*8];
            float4 m1 = *(const float4*)&As[k][tr*8+4];
            float4 n0 = *(const float4*)&Bs[k][tc*8];
            float4 n1 = *(const float4*)&Bs[k][tc*8+4];
            float rm[8] = {m0.x,m0.y,m0.z,m0.w,m1.x,m1.y,m1.z,m1.w};
            float rn[8] = {n0.x,n0.y,n0.z,n0.w,n1.x,n1.y,n1.z,n1.w};
            #pragma unroll
            for (int i = 0; i < 8; i++)
                #pragma unroll
                for (int j = 0; j < 8; j++)
                    acc[i][j] += rm[i] * rn[j];
        }
    }

    #pragma unroll
    for (int i = 0; i < 8; i++) {
        const size_t row = (size_t)bm * 128 + tr * 8 + i;
        float* crow = Cout + row * Nn + bn * 128 + tc * 8;
        #pragma unroll
        for (int j = 0; j < 8; j++) {
            float v = acc[i][j];
            if (MODE == 1) {
                v = 2.0f * (v + bias[bn*128 + tc*8 + j]);
            } else if (MODE == 2) {
                v += bias[bn*128 + tc*8 + j];
                v = 0.5f * v * (1.0f + erff(v * 0.70710678118654752f));
            } else if (MODE == 3) {
                v += bias[bn*128 + tc*8 + j] + res[row * Nn + bn*128 + tc*8 + j];
            }
            crow[j] = v;
        }
    }
}

// ---------------- flash attention: 64-query x 32-key tiles, fp32 -----------
// grid: (b*H + h)*8 + q_tile,  256 threads.
// Thread t: query row r = t/4, group g = t%4.
//   S phase : owns score cols g*8..g*8+8 (of 32)
//   PV phase: owns O cols d = g + 4*i, i=0..15 (strided, conflict-free)
__global__ void __launch_bounds__(256) attn_kernel(const float* __restrict__ qkv,
                                                   float* __restrict__ out)
{
    __shared__ float Qs[64][65];
    __shared__ float Ks[32][65];
    __shared__ float Vs[32][65];
    __shared__ float Ps[64][33];

    const int qt = blockIdx.x & 7;
    const int bh = blockIdx.x >> 3;
    const int h  = bh % H_;
    const int b  = bh / H_;
    const int tid = threadIdx.x;
    const int r = tid >> 2;
    const int g = tid & 3;

    // load Q tile (rows qt*64..+64, head slice)
    {
        const int rr = tid >> 2;
        const int c0 = (tid & 3) * 16;
        const float* src = qkv + ((size_t)(b * N_ + qt * 64 + rr)) * (3 * C_) + h * D_ + c0;
        #pragma unroll
        for (int i = 0; i < 16; i += 4) {
            float4 v = *(const float4*)(src + i);
            Qs[rr][c0+i] = v.x; Qs[rr][c0+i+1] = v.y; Qs[rr][c0+i+2] = v.z; Qs[rr][c0+i+3] = v.w;
        }
    }

    float m_run = -INFINITY, l_run = 0.0f;
    float o_acc[16];
    #pragma unroll
    for (int i = 0; i < 16; i++) o_acc[i] = 0.0f;
    const float scale = 0.125f;   // 1/sqrt(64)

    for (int kt = 0; kt < 16; kt++) {
        __syncthreads();   // previous tile's P/V reads complete
        {
            const int rr = tid >> 3;          // 0..31
            const int c0 = (tid & 7) * 8;     // 0..56
            const float* kr = qkv + ((size_t)(b * N_ + kt * 32 + rr)) * (3 * C_) + C_ + h * D_ + c0;
            const float* vr = kr + C_;
            #pragma unroll
            for (int i = 0; i < 8; i += 4) {
                float4 kv = *(const float4*)(kr + i);
                Ks[rr][c0+i] = kv.x; Ks[rr][c0+i+1] = kv.y; Ks[rr][c0+i+2] = kv.z; Ks[rr][c0+i+3] = kv.w;
                float4 vv = *(const float4*)(vr + i);
                Vs[rr][c0+i] = vv.x; Vs[rr][c0+i+1] = vv.y; Vs[rr][c0+i+2] = vv.z; Vs[rr][c0+i+3] = vv.w;
            }
        }
        __syncthreads();

        // S = Q K^T * scale  (8 cols per thread)
        float s[8];
        #pragma unroll
        for (int c = 0; c < 8; c++) s[c] = 0.0f;
        #pragma unroll
        for (int k = 0; k < 64; k++) {
            float qv = Qs[r][k];
            #pragma unroll
            for (int c = 0; c < 8; c++) s[c] += qv * Ks[g*8+c][k];
        }

        // online softmax update within 4-thread row group
        float mt = -INFINITY;
        #pragma unroll
        for (int c = 0; c < 8; c++) { s[c] *= scale; mt = fmaxf(mt, s[c]); }
        mt = fmaxf(mt, __shfl_xor_sync(0xffffffffu, mt, 1));
        mt = fmaxf(mt, __shfl_xor_sync(0xffffffffu, mt, 2));
        const float m_new = fmaxf(m_run, mt);
        const float alpha = __expf(m_run - m_new);
        float ls = 0.0f;
        #pragma unroll
        for (int c = 0; c < 8; c++) { s[c] = __expf(s[c] - m_new); ls += s[c]; }
        ls += __shfl_xor_sync(0xffffffffu, ls, 1);
        ls += __shfl_xor_sync(0xffffffffu, ls, 2);
        l_run = l_run * alpha + ls;
        m_run = m_new;
        #pragma unroll
        for (int i = 0; i < 16; i++) o_acc[i] *= alpha;
        #pragma unroll
        for (int c = 0; c < 8; c++) Ps[r][g*8+c] = s[c];
        __syncthreads();

        // O += P @ V
        #pragma unroll
        for (int j = 0; j < 32; j++) {
            float p = Ps[r][j];
            #pragma unroll
            for (int i = 0; i < 16; i++) o_acc[i] += p * Vs[j][g + 4*i];
        }
    }

    const float inv = 1.0f / l_run;
    const int n = qt * 64 + r;
    float* dst = out + ((size_t)(b * N_ + n)) * C_ + h * D_;
    #pragma unroll
    for (int i = 0; i < 16; i++) dst[g + 4*i] = o_acc[i] * inv;
}

// ---------------- host launcher -------------------------------------------
extern "C" void kernel_launch(void* const* d_in, const int* in_sizes, int n_in,
                              void* d_out, int out_size)
{
    (void)in_sizes; (void)n_in; (void)out_size;
    const float* x      = (const float*)d_in[0];
    const float* ln1_w  = (const float*)d_in[1];
    const float* ln1_b  = (const float*)d_in[2];
    const float* qkv_w  = (const float*)d_in[3];
    const float* proj_w = (const float*)d_in[4];
    const float* proj_b = (const float*)d_in[5];
    const float* ln2_w  = (const float*)d_in[6];
    const float* ln2_b  = (const float*)d_in[7];
    const float* fc1_w  = (const float*)d_in[8];
    const float* fc1_b  = (const float*)d_in[9];
    const float* fc2_w  = (const float*)d_in[10];
    const float* fc2_b  = (const float*)d_in[11];
    float* out = (float*)d_out;

    float *h1, *qkvb, *attn, *x2, *ln2o, *fc1o;
    cudaGetSymbolAddress((void**)&h1,   g_h1);
    cudaGetSymbolAddress((void**)&qkvb, g_qkv);
    cudaGetSymbolAddress((void**)&attn, g_attn);
    cudaGetSymbolAddress((void**)&x2,   g_x2);
    cudaGetSymbolAddress((void**)&ln2o, g_ln2);
    cudaGetSymbolAddress((void**)&fc1o, g_fc1);

    ln_kernel<<<M_, 256>>>(x, ln1_w, ln1_b, h1);
    gemm_kernel<0><<<dim3(3*C_/128, M_/128), 256>>>(h1, qkv_w, nullptr, nullptr, qkvb, M_, 3*C_, C_);
    attn_kernel<<<B_*H_*8, 256>>>(qkvb, attn);
    gemm_kernel<1><<<dim3(C_/128, M_/128), 256>>>(attn, proj_w, proj_b, nullptr, x2, M_, C_, C_);
    ln_kernel<<<M_, 256>>>(x2, ln2_w, ln2_b, ln2o);
    gemm_kernel<2><<<dim3(HID_/128, M_/128), 256>>>(ln2o, fc1_w, fc1_b, nullptr, fc1o, M_, HID_, C_);
    gemm_kernel<3><<<dim3(C_/128, M_/128), 256>>>(fc1o, fc2_w, fc2_b, x2, out, M_, C_, HID_);
}

// round 4
// speedup vs baseline: 2.2015x; 2.2015x over previous
#include <cuda_runtime.h>
#include <math.h>
#include <stdint.h>

#define B_   32
#define N_   512
#define C_   768
#define H_   12
#define D_   64
#define HID_ 3072
#define M_   (B_*N_)   // 16384 rows

// ---------------- scratch (device globals; no allocation allowed) ----------
__device__ float g_h1  [(size_t)M_ * C_];
__device__ float g_qkv [(size_t)M_ * 3 * C_];
__device__ float g_attn[(size_t)M_ * C_];
__device__ float g_x2  [(size_t)M_ * C_];
__device__ float g_ln2 [(size_t)M_ * C_];
__device__ float g_fc1 [(size_t)M_ * HID_];

// ================= small helpers ===========================================
__device__ __forceinline__ uint32_t smem_u32(const void* p) {
    uint32_t a;
    asm("{ .reg .u64 t; cvta.to.shared.u64 t, %1; cvt.u32.u64 %0, t; }" : "=r"(a) : "l"(p));
    return a;
}
__device__ __forceinline__ void cp16(uint32_t saddr, const void* g) {
    asm volatile("cp.async.cg.shared.global [%0], [%1], 16;" :: "r"(saddr), "l"(g) : "memory");
}
__device__ __forceinline__ uint32_t f2tf32(float f) {
    uint32_t r;
    asm("cvt.rna.tf32.f32 %0, %1;" : "=r"(r) : "f"(f));
    return r;
}
__device__ __forceinline__ void mma_tf32(float* c, const uint32_t* a, const uint32_t* b) {
    asm volatile("mma.sync.aligned.m16n8k8.row.col.f32.tf32.tf32.f32 "
                 "{%0,%1,%2,%3}, {%4,%5,%6,%7}, {%8,%9}, {%0,%1,%2,%3};"
                 : "+f"(c[0]), "+f"(c[1]), "+f"(c[2]), "+f"(c[3])
                 : "r"(a[0]), "r"(a[1]), "r"(a[2]), "r"(a[3]), "r"(b[0]), "r"(b[1]));
}

// ================= tf32 mma.sync GEMM ======================================
// C[M,Nn] = A[M,K] @ W[Nn,K]^T (+epilogue). CTA tile 128x128, BK=32, 8 warps.
// Warp tile 64x32 (4 m-tiles x 4 n-tiles of m16n8k8). 2-stage cp.async.
// MODE 0: plain; 1: 2*(acc+bias); 2: gelu(acc+bias); 3: acc+bias+res
#define BKK 32
#define PAD 36                       // floats per smem row (conflict-free)
#define AS_BYTES (128 * PAD * 4)     // 18432
#define STAGE_B  (2 * AS_BYTES)      // 36864 (A + B)
#define GSMEM    (2 * STAGE_B)       // 73728

template <int MODE>
__global__ void __launch_bounds__(256, 2) tc_gemm(const float* __restrict__ A,
                                                  const float* __restrict__ W,
                                                  const float* __restrict__ bias,
                                                  const float* __restrict__ res,
                                                  float* __restrict__ Cout,
                                                  int M, int Nn, int K)
{
    extern __shared__ float smem[];
    const uint32_t sbase = smem_u32(smem);
    const int tid = threadIdx.x;
    const int bm = blockIdx.y, bn = blockIdx.x;

    const float* Ab = A + (size_t)bm * 128 * K;
    const float* Wb = W + (size_t)bn * 128 * K;
    const int nk = K / BKK;

    const int lrow = tid >> 3;          // 0..31
    const int lch  = (tid & 7) * 4;     // 0,4,...,28

    auto load_stage = [&](int slot, int k0) {
        const uint32_t sA = sbase + slot * STAGE_B;
        const uint32_t sB = sA + AS_BYTES;
        #pragma unroll
        for (int p = 0; p < 4; p++) {
            const int row = lrow + p * 32;
            const uint32_t off = (uint32_t)(row * PAD + lch) * 4u;
            cp16(sA + off, Ab + (size_t)row * K + k0 + lch);
            cp16(sB + off, Wb + (size_t)row * K + k0 + lch);
        }
        asm volatile("cp.async.commit_group;" ::: "memory");
    };

    load_stage(0, 0);
    load_stage(1, BKK);

    const int wid = tid >> 5, lane = tid & 31;
    const int wm = (wid >> 2) * 64;     // 0 / 64
    const int wn = (wid & 3) * 32;      // 0..96
    const int qr = lane >> 2, qc = lane & 3;

    float acc[4][4][4];
    #pragma unroll
    for (int mi = 0; mi < 4; mi++)
        #pragma unroll
        for (int ni = 0; ni < 4; ni++)
            #pragma unroll
            for (int u = 0; u < 4; u++) acc[mi][ni][u] = 0.0f;

    asm volatile("cp.async.wait_group %0;" :: "n"(1) : "memory");
    __syncthreads();

    for (int i = 0; i < nk; i++) {
        const float* sA = smem + (i & 1) * (STAGE_B / 4);
        const float* sB = sA + 128 * PAD;
        #pragma unroll
        for (int kc = 0; kc < 4; kc++) {
            const int kk = kc * 8;
            uint32_t af[4][4];
            #pragma unroll
            for (int mi = 0; mi < 4; mi++) {
                const float* base = sA + (wm + mi * 16 + qr) * PAD + kk + qc;
                af[mi][0] = f2tf32(base[0]);
                af[mi][1] = f2tf32(base[8 * PAD]);
                af[mi][2] = f2tf32(base[4]);
                af[mi][3] = f2tf32(base[8 * PAD + 4]);
            }
            uint32_t bf[4][2];
            #pragma unroll
            for (int ni = 0; ni < 4; ni++) {
                const float* base = sB + (wn + ni * 8 + qr) * PAD + kk + qc;
                bf[ni][0] = f2tf32(base[0]);
                bf[ni][1] = f2tf32(base[4]);
            }
            #pragma unroll
            for (int mi = 0; mi < 4; mi++)
                #pragma unroll
                for (int ni = 0; ni < 4; ni++)
                    mma_tf32(acc[mi][ni], af[mi], bf[ni]);
        }
        __syncthreads();                       // everyone done reading slot i&1
        if (i + 1 < nk) {
            if (i + 2 < nk) {
                load_stage(i & 1, (i + 2) * BKK);
                asm volatile("cp.async.wait_group %0;" :: "n"(1) : "memory");
            } else {
                asm volatile("cp.async.wait_group %0;" :: "n"(0) : "memory");
            }
            __syncthreads();
        }
    }

    // ---- epilogue ----
    #pragma unroll
    for (int mi = 0; mi < 4; mi++) {
        #pragma unroll
        for (int ni = 0; ni < 4; ni++) {
            const int col = bn * 128 + wn + ni * 8 + 2 * qc;
            #pragma unroll
            for (int half = 0; half < 2; half++) {
                const size_t row = (size_t)bm * 128 + wm + mi * 16 + qr + half * 8;
                float v0 = acc[mi][ni][half * 2 + 0];
                float v1 = acc[mi][ni][half * 2 + 1];
                if (MODE == 1) {
                    v0 = 2.0f * (v0 + bias[col]);
                    v1 = 2.0f * (v1 + bias[col + 1]);
                } else if (MODE == 2) {
                    v0 += bias[col];
                    v1 += bias[col + 1];
                    v0 = 0.5f * v0 * (1.0f + erff(v0 * 0.70710678118654752f));
                    v1 = 0.5f * v1 * (1.0f + erff(v1 * 0.70710678118654752f));
                } else if (MODE == 3) {
                    const float* rr = res + row * Nn + col;
                    v0 += bias[col] + rr[0];
                    v1 += bias[col + 1] + rr[1];
                }
                *(float2*)(Cout + row * Nn + col) = make_float2(v0, v1);
            }
        }
    }
}

// ---------------- fused LayerNorm: one block per row, C=768=3*256 ----------
__global__ void __launch_bounds__(256) ln_kernel(const float* __restrict__ x,
                                                 const float* __restrict__ w,
                                                 const float* __restrict__ b,
                                                 float* __restrict__ out)
{
    __shared__ float red[8];
    const int row = blockIdx.x;
    const int t   = threadIdx.x;
    const float* xr = x + (size_t)row * C_;

    float v0 = xr[t], v1 = xr[t + 256], v2 = xr[t + 512];
    float s = v0 + v1 + v2;
    #pragma unroll
    for (int o = 16; o; o >>= 1) s += __shfl_xor_sync(0xffffffffu, s, o);
    if ((t & 31) == 0) red[t >> 5] = s;
    __syncthreads();
    float tot = red[0]+red[1]+red[2]+red[3]+red[4]+red[5]+red[6]+red[7];
    const float mu = tot * (1.0f / C_);

    float d0 = v0 - mu, d1 = v1 - mu, d2 = v2 - mu;
    float q = d0*d0 + d1*d1 + d2*d2;
    #pragma unroll
    for (int o = 16; o; o >>= 1) q += __shfl_xor_sync(0xffffffffu, q, o);
    __syncthreads();
    if ((t & 31) == 0) red[t >> 5] = q;
    __syncthreads();
    float var = (red[0]+red[1]+red[2]+red[3]+red[4]+red[5]+red[6]+red[7]) * (1.0f / C_);
    const float rstd = rsqrtf(var + 1e-5f);

    float* orow = out + (size_t)row * C_;
    orow[t]       = d0 * rstd * w[t]       + b[t];
    orow[t + 256] = d1 * rstd * w[t + 256] + b[t + 256];
    orow[t + 512] = d2 * rstd * w[t + 512] + b[t + 512];
}

// ---------------- flash attention: 64-query x 32-key tiles, fp32 -----------
__global__ void __launch_bounds__(256) attn_kernel(const float* __restrict__ qkv,
                                                   float* __restrict__ out)
{
    __shared__ float Qs[64][65];
    __shared__ float Ks[32][65];
    __shared__ float Vs[32][65];
    __shared__ float Ps[64][33];

    const int qt = blockIdx.x & 7;
    const int bh = blockIdx.x >> 3;
    const int h  = bh % H_;
    const int b  = bh / H_;
    const int tid = threadIdx.x;
    const int r = tid >> 2;
    const int g = tid & 3;

    {
        const int rr = tid >> 2;
        const int c0 = (tid & 3) * 16;
        const float* src = qkv + ((size_t)(b * N_ + qt * 64 + rr)) * (3 * C_) + h * D_ + c0;
        #pragma unroll
        for (int i = 0; i < 16; i += 4) {
            float4 v = *(const float4*)(src + i);
            Qs[rr][c0+i] = v.x; Qs[rr][c0+i+1] = v.y; Qs[rr][c0+i+2] = v.z; Qs[rr][c0+i+3] = v.w;
        }
    }

    float m_run = -INFINITY, l_run = 0.0f;
    float o_acc[16];
    #pragma unroll
    for (int i = 0; i < 16; i++) o_acc[i] = 0.0f;
    const float scale = 0.125f;

    for (int kt = 0; kt < 16; kt++) {
        __syncthreads();
        {
            const int rr = tid >> 3;
            const int c0 = (tid & 7) * 8;
            const float* kr = qkv + ((size_t)(b * N_ + kt * 32 + rr)) * (3 * C_) + C_ + h * D_ + c0;
            const float* vr = kr + C_;
            #pragma unroll
            for (int i = 0; i < 8; i += 4) {
                float4 kv = *(const float4*)(kr + i);
                Ks[rr][c0+i] = kv.x; Ks[rr][c0+i+1] = kv.y; Ks[rr][c0+i+2] = kv.z; Ks[rr][c0+i+3] = kv.w;
                float4 vv = *(const float4*)(vr + i);
                Vs[rr][c0+i] = vv.x; Vs[rr][c0+i+1] = vv.y; Vs[rr][c0+i+2] = vv.z; Vs[rr][c0+i+3] = vv.w;
            }
        }
        __syncthreads();

        float s[8];
        #pragma unroll
        for (int c = 0; c < 8; c++) s[c] = 0.0f;
        #pragma unroll
        for (int k = 0; k < 64; k++) {
            float qv = Qs[r][k];
            #pragma unroll
            for (int c = 0; c < 8; c++) s[c] += qv * Ks[g*8+c][k];
        }

        float mt = -INFINITY;
        #pragma unroll
        for (int c = 0; c < 8; c++) { s[c] *= scale; mt = fmaxf(mt, s[c]); }
        mt = fmaxf(mt, __shfl_xor_sync(0xffffffffu, mt, 1));
        mt = fmaxf(mt, __shfl_xor_sync(0xffffffffu, mt, 2));
        const float m_new = fmaxf(m_run, mt);
        const float alpha = __expf(m_run - m_new);
        float ls = 0.0f;
        #pragma unroll
        for (int c = 0; c < 8; c++) { s[c] = __expf(s[c] - m_new); ls += s[c]; }
        ls += __shfl_xor_sync(0xffffffffu, ls, 1);
        ls += __shfl_xor_sync(0xffffffffu, ls, 2);
        l_run = l_run * alpha + ls;
        m_run = m_new;
        #pragma unroll
        for (int i = 0; i < 16; i++) o_acc[i] *= alpha;
        #pragma unroll
        for (int c = 0; c < 8; c++) Ps[r][g*8+c] = s[c];
        __syncthreads();

        #pragma unroll
        for (int j = 0; j < 32; j++) {
            float p = Ps[r][j];
            #pragma unroll
            for (int i = 0; i < 16; i++) o_acc[i] += p * Vs[j][g + 4*i];
        }
    }

    const float inv = 1.0f / l_run;
    const int n = qt * 64 + r;
    float* dst = out + ((size_t)(b * N_ + n)) * C_ + h * D_;
    #pragma unroll
    for (int i = 0; i < 16; i++) dst[g + 4*i] = o_acc[i] * inv;
}

// ---------------- host launcher -------------------------------------------
extern "C" void kernel_launch(void* const* d_in, const int* in_sizes, int n_in,
                              void* d_out, int out_size)
{
    (void)in_sizes; (void)n_in; (void)out_size;
    const float* x      = (const float*)d_in[0];
    const float* ln1_w  = (const float*)d_in[1];
    const float* ln1_b  = (const float*)d_in[2];
    const float* qkv_w  = (const float*)d_in[3];
    const float* proj_w = (const float*)d_in[4];
    const float* proj_b = (const float*)d_in[5];
    const float* ln2_w  = (const float*)d_in[6];
    const float* ln2_b  = (const float*)d_in[7];
    const float* fc1_w  = (const float*)d_in[8];
    const float* fc1_b  = (const float*)d_in[9];
    const float* fc2_w  = (const float*)d_in[10];
    const float* fc2_b  = (const float*)d_in[11];
    float* out = (float*)d_out;

    float *h1, *qkvb, *attn, *x2, *ln2o, *fc1o;
    cudaGetSymbolAddress((void**)&h1,   g_h1);
    cudaGetSymbolAddress((void**)&qkvb, g_qkv);
    cudaGetSymbolAddress((void**)&attn, g_attn);
    cudaGetSymbolAddress((void**)&x2,   g_x2);
    cudaGetSymbolAddress((void**)&ln2o, g_ln2);
    cudaGetSymbolAddress((void**)&fc1o, g_fc1);

    static bool attr_done = false;
    if (!attr_done) {
        cudaFuncSetAttribute(tc_gemm<0>, cudaFuncAttributeMaxDynamicSharedMemorySize, GSMEM);
        cudaFuncSetAttribute(tc_gemm<1>, cudaFuncAttributeMaxDynamicSharedMemorySize, GSMEM);
        cudaFuncSetAttribute(tc_gemm<2>, cudaFuncAttributeMaxDynamicSharedMemorySize, GSMEM);
        cudaFuncSetAttribute(tc_gemm<3>, cudaFuncAttributeMaxDynamicSharedMemorySize, GSMEM);
        attr_done = true;
    }

    ln_kernel<<<M_, 256>>>(x, ln1_w, ln1_b, h1);
    tc_gemm<0><<<dim3(3*C_/128, M_/128), 256, GSMEM>>>(h1, qkv_w, nullptr, nullptr, qkvb, M_, 3*C_, C_);
    attn_kernel<<<B_*H_*8, 256>>>(qkvb, attn);
    tc_gemm<1><<<dim3(C_/128, M_/128), 256, GSMEM>>>(attn, proj_w, proj_b, nullptr, x2, M_, C_, C_);
    ln_kernel<<<M_, 256>>>(x2, ln2_w, ln2_b, ln2o);
    tc_gemm<2><<<dim3(HID_/128, M_/128), 256, GSMEM>>>(ln2o, fc1_w, fc1_b, nullptr, fc1o, M_, HID_, C_);
    tc_gemm<3><<<dim3(C_/128, M_/128), 256, GSMEM>>>(fc1o, fc2_w, fc2_b, x2, out, M_, C_, HID_);
}

// round 5
// speedup vs baseline: 3.3646x; 1.5283x over previous
#include <cuda_runtime.h>
#include <math.h>
#include <stdint.h>

#define B_   32
#define N_   512
#define C_   768
#define H_   12
#define D_   64
#define HID_ 3072
#define M_   (B_*N_)   // 16384 rows

// ---------------- scratch (device globals; no allocation allowed) ----------
__device__ float g_h1  [(size_t)M_ * C_];
__device__ float g_qkv [(size_t)M_ * 3 * C_];
__device__ float g_attn[(size_t)M_ * C_];
__device__ float g_x2  [(size_t)M_ * C_];
__device__ float g_ln2 [(size_t)M_ * C_];
__device__ float g_fc1 [(size_t)M_ * HID_];
// tf32-rounded weights: qkv_w | proj_w | fc1_w | fc2_w
#define RW_QKV 0
#define RW_PROJ (3*C_*C_)                 // 1769472
#define RW_FC1  (RW_PROJ + C_*C_)         // 2359296
#define RW_FC2  (RW_FC1 + HID_*C_)        // 4718592
__device__ float g_rw[(size_t)RW_FC2 + (size_t)C_*HID_];

// ================= small helpers ===========================================
__device__ __forceinline__ void cp16(uint32_t saddr, const void* g) {
    asm volatile("cp.async.cg.shared.global [%0], [%1], 16;" :: "r"(saddr), "l"(g) : "memory");
}
__device__ __forceinline__ uint32_t smem_u32(const void* p) {
    uint32_t a;
    asm("{ .reg .u64 t; cvta.to.shared.u64 t, %1; cvt.u32.u64 %0, t; }" : "=r"(a) : "l"(p));
    return a;
}
__device__ __forceinline__ uint32_t f2tf32(float f) {
    uint32_t r;
    asm("cvt.rna.tf32.f32 %0, %1;" : "=r"(r) : "f"(f));
    return r;
}
__device__ __forceinline__ float tf32r(float f) { return __uint_as_float(f2tf32(f)); }
__device__ __forceinline__ void split2(float v, uint32_t& hi, uint32_t& lo) {
    hi = f2tf32(v);
    lo = f2tf32(v - __uint_as_float(hi));
}
__device__ __forceinline__ void mma_tf32(float* c, const uint32_t* a, const uint32_t* b) {
    asm volatile("mma.sync.aligned.m16n8k8.row.col.f32.tf32.tf32.f32 "
                 "{%0,%1,%2,%3}, {%4,%5,%6,%7}, {%8,%9}, {%0,%1,%2,%3};"
                 : "+f"(c[0]), "+f"(c[1]), "+f"(c[2]), "+f"(c[3])
                 : "r"(a[0]), "r"(a[1]), "r"(a[2]), "r"(a[3]), "r"(b[0]), "r"(b[1]));
}

// ================= weight tf32 pre-round ===================================
__global__ void __launch_bounds__(256) round_tf32_kernel(const float* __restrict__ in,
                                                         float* __restrict__ out, int n)
{
    int i = (blockIdx.x * 256 + threadIdx.x) * 4;
    if (i < n) {
        float4 v = *(const float4*)(in + i);
        v.x = tf32r(v.x); v.y = tf32r(v.y); v.z = tf32r(v.z); v.w = tf32r(v.w);
        *(float4*)(out + i) = v;
    }
}

// ================= tf32 mma.sync GEMM ======================================
// Inputs (A and W) are pre-rounded to tf32 by producers.
// C[M,Nn] = A[M,K] @ W[Nn,K]^T (+epilogue). CTA 128x128, BK=32, 8 warps.
// MODE 0: plain; 1: 2*(acc+bias); 2: gelu(acc+bias) [tf32-rounded out]; 3: acc+bias+res
#define BKK 32
#define PAD 36
#define AS_BYTES (128 * PAD * 4)
#define STAGE_B  (2 * AS_BYTES)
#define GSMEM    (2 * STAGE_B)

template <int MODE>
__global__ void __launch_bounds__(256, 2) tc_gemm(const float* __restrict__ A,
                                                  const float* __restrict__ W,
                                                  const float* __restrict__ bias,
                                                  const float* __restrict__ res,
                                                  float* __restrict__ Cout,
                                                  int M, int Nn, int K)
{
    extern __shared__ float smem[];
    const uint32_t sbase = smem_u32(smem);
    const int tid = threadIdx.x;
    const int bm = blockIdx.y, bn = blockIdx.x;

    const float* Ab = A + (size_t)bm * 128 * K;
    const float* Wb = W + (size_t)bn * 128 * K;
    const int nk = K / BKK;

    const int lrow = tid >> 3;
    const int lch  = (tid & 7) * 4;

    auto load_stage = [&](int slot, int k0) {
        const uint32_t sA = sbase + slot * STAGE_B;
        const uint32_t sB = sA + AS_BYTES;
        #pragma unroll
        for (int p = 0; p < 4; p++) {
            const int row = lrow + p * 32;
            const uint32_t off = (uint32_t)(row * PAD + lch) * 4u;
            cp16(sA + off, Ab + (size_t)row * K + k0 + lch);
            cp16(sB + off, Wb + (size_t)row * K + k0 + lch);
        }
        asm volatile("cp.async.commit_group;" ::: "memory");
    };

    load_stage(0, 0);
    load_stage(1, BKK);

    const int wid = tid >> 5, lane = tid & 31;
    const int wm = (wid >> 2) * 64;
    const int wn = (wid & 3) * 32;
    const int qr = lane >> 2, qc = lane & 3;

    float acc[4][4][4];
    #pragma unroll
    for (int mi = 0; mi < 4; mi++)
        #pragma unroll
        for (int ni = 0; ni < 4; ni++)
            #pragma unroll
            for (int u = 0; u < 4; u++) acc[mi][ni][u] = 0.0f;

    asm volatile("cp.async.wait_group %0;" :: "n"(1) : "memory");
    __syncthreads();

    for (int i = 0; i < nk; i++) {
        const float* sA = smem + (i & 1) * (STAGE_B / 4);
        const float* sB = sA + 128 * PAD;
        #pragma unroll
        for (int kc = 0; kc < 4; kc++) {
            const int kk = kc * 8;
            uint32_t af[4][4];
            #pragma unroll
            for (int mi = 0; mi < 4; mi++) {
                const uint32_t* base = (const uint32_t*)(sA + (wm + mi * 16 + qr) * PAD + kk + qc);
                af[mi][0] = base[0];
                af[mi][1] = base[8 * PAD];
                af[mi][2] = base[4];
                af[mi][3] = base[8 * PAD + 4];
            }
            uint32_t bf[4][2];
            #pragma unroll
            for (int ni = 0; ni < 4; ni++) {
                const uint32_t* base = (const uint32_t*)(sB + (wn + ni * 8 + qr) * PAD + kk + qc);
                bf[ni][0] = base[0];
                bf[ni][1] = base[4];
            }
            #pragma unroll
            for (int mi = 0; mi < 4; mi++)
                #pragma unroll
                for (int ni = 0; ni < 4; ni++)
                    mma_tf32(acc[mi][ni], af[mi], bf[ni]);
        }
        __syncthreads();
        if (i + 1 < nk) {
            if (i + 2 < nk) {
                load_stage(i & 1, (i + 2) * BKK);
                asm volatile("cp.async.wait_group %0;" :: "n"(1) : "memory");
            } else {
                asm volatile("cp.async.wait_group %0;" :: "n"(0) : "memory");
            }
            __syncthreads();
        }
    }

    #pragma unroll
    for (int mi = 0; mi < 4; mi++) {
        #pragma unroll
        for (int ni = 0; ni < 4; ni++) {
            const int col = bn * 128 + wn + ni * 8 + 2 * qc;
            #pragma unroll
            for (int half = 0; half < 2; half++) {
                const size_t row = (size_t)bm * 128 + wm + mi * 16 + qr + half * 8;
                float v0 = acc[mi][ni][half * 2 + 0];
                float v1 = acc[mi][ni][half * 2 + 1];
                if (MODE == 1) {
                    v0 = 2.0f * (v0 + bias[col]);
                    v1 = 2.0f * (v1 + bias[col + 1]);
                } else if (MODE == 2) {
                    v0 += bias[col];
                    v1 += bias[col + 1];
                    v0 = 0.5f * v0 * (1.0f + erff(v0 * 0.70710678118654752f));
                    v1 = 0.5f * v1 * (1.0f + erff(v1 * 0.70710678118654752f));
                    v0 = tf32r(v0);   // feeds fc2 GEMM
                    v1 = tf32r(v1);
                } else if (MODE == 3) {
                    const float* rr = res + row * Nn + col;
                    v0 += bias[col] + rr[0];
                    v1 += bias[col + 1] + rr[1];
                }
                *(float2*)(Cout + row * Nn + col) = make_float2(v0, v1);
            }
        }
    }
}

// ---------------- fused LayerNorm (output tf32-rounded: feeds GEMMs) -------
__global__ void __launch_bounds__(256) ln_kernel(const float* __restrict__ x,
                                                 const float* __restrict__ w,
                                                 const float* __restrict__ b,
                                                 float* __restrict__ out)
{
    __shared__ float red[8];
    const int row = blockIdx.x;
    const int t   = threadIdx.x;
    const float* xr = x + (size_t)row * C_;

    float v0 = xr[t], v1 = xr[t + 256], v2 = xr[t + 512];
    float s = v0 + v1 + v2;
    #pragma unroll
    for (int o = 16; o; o >>= 1) s += __shfl_xor_sync(0xffffffffu, s, o);
    if ((t & 31) == 0) red[t >> 5] = s;
    __syncthreads();
    float tot = red[0]+red[1]+red[2]+red[3]+red[4]+red[5]+red[6]+red[7];
    const float mu = tot * (1.0f / C_);

    float d0 = v0 - mu, d1 = v1 - mu, d2 = v2 - mu;
    float q = d0*d0 + d1*d1 + d2*d2;
    #pragma unroll
    for (int o = 16; o; o >>= 1) q += __shfl_xor_sync(0xffffffffu, q, o);
    __syncthreads();
    if ((t & 31) == 0) red[t >> 5] = q;
    __syncthreads();
    float var = (red[0]+red[1]+red[2]+red[3]+red[4]+red[5]+red[6]+red[7]) * (1.0f / C_);
    const float rstd = rsqrtf(var + 1e-5f);

    float* orow = out + (size_t)row * C_;
    orow[t]       = tf32r(d0 * rstd * w[t]       + b[t]);
    orow[t + 256] = tf32r(d1 * rstd * w[t + 256] + b[t + 256]);
    orow[t + 512] = tf32r(d2 * rstd * w[t + 512] + b[t + 512]);
}

// ================= flash attention, split-tf32 mma.sync ====================
// Block: 128 query rows (8 warps, warp = 16 rows), key tiles of 64.
// Split precision: X = Xh + Xl (tf32 pair); X*Y = Xh*Yh + Xh*Yl + Xl*Yh.
#define AT_S 72
#define AT_Q 0
#define AT_K 9216
#define AT_V 13824
#define AT_P 18432
#define ATT_SMEM ((18432 + 9216) * 4)   // 110592 B

__global__ void __launch_bounds__(256, 2) attn_mma(const float* __restrict__ qkv,
                                                   float* __restrict__ out)
{
    extern __shared__ float sm[];
    float* Qs = sm + AT_Q;
    float* Ks = sm + AT_K;
    float* Vs = sm + AT_V;
    float* Ps = sm + AT_P;

    const int qt = blockIdx.x;          // 0..3
    const int bh = blockIdx.y;          // b*H + h
    const int h  = bh % H_;
    const int b  = bh / H_;
    const int tid = threadIdx.x;
    const int w = tid >> 5, lane = tid & 31;
    const int qr = lane >> 2, qc = lane & 3;
    const int mrow = w * 16;
    const size_t rowbase = (size_t)b * N_ + (size_t)qt * 128;

    // stage Q tile (128 x 64)
    #pragma unroll
    for (int t = 0; t < 8; t++) {
        int i = tid + t * 256;                 // 2048 float4 units
        int row = i >> 4, c4 = (i & 15) * 4;
        float4 v = *(const float4*)(qkv + (rowbase + row) * (3 * C_) + h * D_ + c4);
        *(float4*)(Qs + row * AT_S + c4) = v;
    }
    __syncthreads();

    float m0 = -INFINITY, m1 = -INFINITY, l0 = 0.0f, l1 = 0.0f;
    float O[8][4];
    #pragma unroll
    for (int nt = 0; nt < 8; nt++)
        #pragma unroll
        for (int u = 0; u < 4; u++) O[nt][u] = 0.0f;

    for (int kt = 0; kt < 8; kt++) {
        __syncthreads();   // prior tile's K/V reads done
        #pragma unroll
        for (int t = 0; t < 4; t++) {
            int i = tid + t * 256;             // 1024 float4 units
            int row = i >> 4, c4 = (i & 15) * 4;
            const float* src = qkv + ((size_t)b * N_ + kt * 64 + row) * (3 * C_) + C_ + h * D_ + c4;
            *(float4*)(Ks + row * AT_S + c4) = *(const float4*)src;
            *(float4*)(Vs + row * AT_S + c4) = *(const float4*)(src + C_);
        }
        __syncthreads();

        // ---- S = Q K^T (split tf32) ----
        float S[8][4];
        #pragma unroll
        for (int nt = 0; nt < 8; nt++)
            #pragma unroll
            for (int u = 0; u < 4; u++) S[nt][u] = 0.0f;

        #pragma unroll
        for (int kk = 0; kk < 8; kk++) {
            const float* qb = Qs + (mrow + qr) * AT_S + kk * 8 + qc;
            uint32_t ah[4], al[4];
            split2(qb[0], ah[0], al[0]);
            split2(qb[8 * AT_S], ah[1], al[1]);
            split2(qb[4], ah[2], al[2]);
            split2(qb[8 * AT_S + 4], ah[3], al[3]);
            #pragma unroll
            for (int nt = 0; nt < 8; nt++) {
                const float* kb = Ks + (nt * 8 + qr) * AT_S + kk * 8 + qc;
                uint32_t bh2[2], bl2[2];
                split2(kb[0], bh2[0], bl2[0]);
                split2(kb[4], bh2[1], bl2[1]);
                mma_tf32(S[nt], ah, bh2);
                mma_tf32(S[nt], ah, bl2);
                mma_tf32(S[nt], al, bh2);
            }
        }

        // ---- online softmax ----
        float mt0 = -INFINITY, mt1 = -INFINITY;
        #pragma unroll
        for (int nt = 0; nt < 8; nt++) {
            #pragma unroll
            for (int u = 0; u < 4; u++) S[nt][u] *= 0.125f;
            mt0 = fmaxf(mt0, fmaxf(S[nt][0], S[nt][1]));
            mt1 = fmaxf(mt1, fmaxf(S[nt][2], S[nt][3]));
        }
        mt0 = fmaxf(mt0, __shfl_xor_sync(0xffffffffu, mt0, 1));
        mt0 = fmaxf(mt0, __shfl_xor_sync(0xffffffffu, mt0, 2));
        mt1 = fmaxf(mt1, __shfl_xor_sync(0xffffffffu, mt1, 1));
        mt1 = fmaxf(mt1, __shfl_xor_sync(0xffffffffu, mt1, 2));
        const float mn0 = fmaxf(m0, mt0), mn1 = fmaxf(m1, mt1);
        const float a0 = __expf(m0 - mn0), a1 = __expf(m1 - mn1);
        float ls0 = 0.0f, ls1 = 0.0f;
        #pragma unroll
        for (int nt = 0; nt < 8; nt++) {
            S[nt][0] = __expf(S[nt][0] - mn0);
            S[nt][1] = __expf(S[nt][1] - mn0);
            S[nt][2] = __expf(S[nt][2] - mn1);
            S[nt][3] = __expf(S[nt][3] - mn1);
            ls0 += S[nt][0] + S[nt][1];
            ls1 += S[nt][2] + S[nt][3];
        }
        ls0 += __shfl_xor_sync(0xffffffffu, ls0, 1);
        ls0 += __shfl_xor_sync(0xffffffffu, ls0, 2);
        ls1 += __shfl_xor_sync(0xffffffffu, ls1, 1);
        ls1 += __shfl_xor_sync(0xffffffffu, ls1, 2);
        l0 = l0 * a0 + ls0;
        l1 = l1 * a1 + ls1;
        m0 = mn0; m1 = mn1;
        #pragma unroll
        for (int nt = 0; nt < 8; nt++) {
            O[nt][0] *= a0; O[nt][1] *= a0;
            O[nt][2] *= a1; O[nt][3] *= a1;
        }

        // ---- write P (per-warp private rows) ----
        #pragma unroll
        for (int nt = 0; nt < 8; nt++) {
            *(float2*)(Ps + (mrow + qr) * AT_S + nt * 8 + 2 * qc)     = make_float2(S[nt][0], S[nt][1]);
            *(float2*)(Ps + (mrow + qr + 8) * AT_S + nt * 8 + 2 * qc) = make_float2(S[nt][2], S[nt][3]);
        }
        __syncwarp();

        // ---- O += P V (split tf32) ----
        #pragma unroll
        for (int kk = 0; kk < 8; kk++) {
            const float* pb = Ps + (mrow + qr) * AT_S + kk * 8 + qc;
            uint32_t ph[4], pl[4];
            split2(pb[0], ph[0], pl[0]);
            split2(pb[8 * AT_S], ph[1], pl[1]);
            split2(pb[4], ph[2], pl[2]);
            split2(pb[8 * AT_S + 4], ph[3], pl[3]);
            #pragma unroll
            for (int nt = 0; nt < 8; nt++) {
                const float* vb = Vs + (kk * 8 + qc) * AT_S + nt * 8 + qr;
                uint32_t vh2[2], vl2[2];
                split2(vb[0], vh2[0], vl2[0]);
                split2(vb[4 * AT_S], vh2[1], vl2[1]);
                mma_tf32(O[nt], ph, vh2);
                mma_tf32(O[nt], ph, vl2);
                mma_tf32(O[nt], pl, vh2);
            }
        }
    }

    // ---- store O (tf32-rounded: feeds proj GEMM) ----
    const float inv0 = 1.0f / l0, inv1 = 1.0f / l1;
    #pragma unroll
    for (int nt = 0; nt < 8; nt++) {
        const int col = h * D_ + nt * 8 + 2 * qc;
        const size_t r0 = rowbase + mrow + qr;
        *(float2*)(out + r0 * C_ + col) =
            make_float2(tf32r(O[nt][0] * inv0), tf32r(O[nt][1] * inv0));
        *(float2*)(out + (r0 + 8) * C_ + col) =
            make_float2(tf32r(O[nt][2] * inv1), tf32r(O[nt][3] * inv1));
    }
}

// ---------------- host launcher -------------------------------------------
extern "C" void kernel_launch(void* const* d_in, const int* in_sizes, int n_in,
                              void* d_out, int out_size)
{
    (void)in_sizes; (void)n_in; (void)out_size;
    const float* x      = (const float*)d_in[0];
    const float* ln1_w  = (const float*)d_in[1];
    const float* ln1_b  = (const float*)d_in[2];
    const float* qkv_w  = (const float*)d_in[3];
    const float* proj_w = (const float*)d_in[4];
    const float* proj_b = (const float*)d_in[5];
    const float* ln2_w  = (const float*)d_in[6];
    const float* ln2_b  = (const float*)d_in[7];
    const float* fc1_w  = (const float*)d_in[8];
    const float* fc1_b  = (const float*)d_in[9];
    const float* fc2_w  = (const float*)d_in[10];
    const float* fc2_b  = (const float*)d_in[11];
    float* out = (float*)d_out;

    float *h1, *qkvb, *attn, *x2, *ln2o, *fc1o, *rw;
    cudaGetSymbolAddress((void**)&h1,   g_h1);
    cudaGetSymbolAddress((void**)&qkvb, g_qkv);
    cudaGetSymbolAddress((void**)&attn, g_attn);
    cudaGetSymbolAddress((void**)&x2,   g_x2);
    cudaGetSymbolAddress((void**)&ln2o, g_ln2);
    cudaGetSymbolAddress((void**)&fc1o, g_fc1);
    cudaGetSymbolAddress((void**)&rw,   g_rw);

    static bool attr_done = false;
    if (!attr_done) {
        cudaFuncSetAttribute(tc_gemm<0>, cudaFuncAttributeMaxDynamicSharedMemorySize, GSMEM);
        cudaFuncSetAttribute(tc_gemm<1>, cudaFuncAttributeMaxDynamicSharedMemorySize, GSMEM);
        cudaFuncSetAttribute(tc_gemm<2>, cudaFuncAttributeMaxDynamicSharedMemorySize, GSMEM);
        cudaFuncSetAttribute(tc_gemm<3>, cudaFuncAttributeMaxDynamicSharedMemorySize, GSMEM);
        cudaFuncSetAttribute(attn_mma,   cudaFuncAttributeMaxDynamicSharedMemorySize, ATT_SMEM);
        attr_done = true;
    }

    // weight pre-round (tf32)
    round_tf32_kernel<<<(3*C_*C_/4 + 255)/256, 256>>>(qkv_w,  rw + RW_QKV,  3*C_*C_);
    round_tf32_kernel<<<(C_*C_/4   + 255)/256, 256>>>(proj_w, rw + RW_PROJ, C_*C_);
    round_tf32_kernel<<<(HID_*C_/4 + 255)/256, 256>>>(fc1_w,  rw + RW_FC1,  HID_*C_);
    round_tf32_kernel<<<(C_*HID_/4 + 255)/256, 256>>>(fc2_w,  rw + RW_FC2,  C_*HID_);

    ln_kernel<<<M_, 256>>>(x, ln1_w, ln1_b, h1);
    tc_gemm<0><<<dim3(3*C_/128, M_/128), 256, GSMEM>>>(h1, rw + RW_QKV, nullptr, nullptr, qkvb, M_, 3*C_, C_);
    attn_mma<<<dim3(4, B_*H_), 256, ATT_SMEM>>>(qkvb, attn);
    tc_gemm<1><<<dim3(C_/128, M_/128), 256, GSMEM>>>(attn, rw + RW_PROJ, proj_b, nullptr, x2, M_, C_, C_);
    ln_kernel<<<M_, 256>>>(x2, ln2_w, ln2_b, ln2o);
    tc_gemm<2><<<dim3(HID_/128, M_/128), 256, GSMEM>>>(ln2o, rw + RW_FC1, fc1_b, nullptr, fc1o, M_, HID_, C_);
    tc_gemm<3><<<dim3(C_/128, M_/128), 256, GSMEM>>>(fc1o, rw + RW_FC2, fc2_b, x2, out, M_, C_, HID_);
}

// round 6
// speedup vs baseline: 3.6720x; 1.0914x over previous
#include <cuda_runtime.h>
#include <math.h>
#include <stdint.h>

#define B_   32
#define N_   512
#define C_   768
#define H_   12
#define D_   64
#define HID_ 3072
#define M_   (B_*N_)   // 16384 rows

// ---------------- scratch (device globals; no allocation allowed) ----------
__device__ float g_h1  [(size_t)M_ * C_];
__device__ float g_qkv [(size_t)M_ * 3 * C_];
__device__ float g_attn[(size_t)M_ * C_];
__device__ float g_x2  [(size_t)M_ * C_];
__device__ float g_ln2 [(size_t)M_ * C_];
__device__ float g_fc1 [(size_t)M_ * HID_];
// tf32-rounded weights: qkv_w | proj_w | fc1_w | fc2_w
#define RW_QKV 0
#define RW_PROJ (3*C_*C_)
#define RW_FC1  (RW_PROJ + C_*C_)
#define RW_FC2  (RW_FC1 + HID_*C_)
#define RW_TOT  (RW_FC2 + C_*HID_)       // 7077888
__device__ float g_rw[(size_t)RW_TOT];

// ================= small helpers ===========================================
__device__ __forceinline__ void cp16(uint32_t saddr, const void* g) {
    asm volatile("cp.async.cg.shared.global [%0], [%1], 16;" :: "r"(saddr), "l"(g) : "memory");
}
__device__ __forceinline__ uint32_t smem_u32(const void* p) {
    uint32_t a;
    asm("{ .reg .u64 t; cvta.to.shared.u64 t, %1; cvt.u32.u64 %0, t; }" : "=r"(a) : "l"(p));
    return a;
}
__device__ __forceinline__ uint32_t f2tf32(float f) {
    uint32_t r;
    asm("cvt.rna.tf32.f32 %0, %1;" : "=r"(r) : "f"(f));
    return r;
}
__device__ __forceinline__ float tf32r(float f) { return __uint_as_float(f2tf32(f)); }
__device__ __forceinline__ void split2(float v, uint32_t& hi, uint32_t& lo) {
    hi = f2tf32(v);
    lo = f2tf32(v - __uint_as_float(hi));
}
__device__ __forceinline__ void mma_tf32(float* c, const uint32_t* a, const uint32_t* b) {
    asm volatile("mma.sync.aligned.m16n8k8.row.col.f32.tf32.tf32.f32 "
                 "{%0,%1,%2,%3}, {%4,%5,%6,%7}, {%8,%9}, {%0,%1,%2,%3};"
                 : "+f"(c[0]), "+f"(c[1]), "+f"(c[2]), "+f"(c[3])
                 : "r"(a[0]), "r"(a[1]), "r"(a[2]), "r"(a[3]), "r"(b[0]), "r"(b[1]));
}
__device__ __forceinline__ void ldsm_x4(uint32_t* r, uint32_t addr) {
    asm volatile("ldmatrix.sync.aligned.m8n8.x4.shared.b16 {%0,%1,%2,%3}, [%4];"
                 : "=r"(r[0]), "=r"(r[1]), "=r"(r[2]), "=r"(r[3]) : "r"(addr));
}
__device__ __forceinline__ void ldsm_x2(uint32_t* r, uint32_t addr) {
    asm volatile("ldmatrix.sync.aligned.m8n8.x2.shared.b16 {%0,%1}, [%2];"
                 : "=r"(r[0]), "=r"(r[1]) : "r"(addr));
}

// ================= weight tf32 pre-round (single kernel) ===================
__global__ void __launch_bounds__(256) round_all_kernel(const float* __restrict__ w0,
                                                        const float* __restrict__ w1,
                                                        const float* __restrict__ w2,
                                                        const float* __restrict__ w3,
                                                        float* __restrict__ out)
{
    const size_t i = ((size_t)blockIdx.x * 256 + threadIdx.x) * 4;
    if (i >= (size_t)RW_TOT) return;
    const float* src;
    size_t off;
    if (i < (size_t)RW_PROJ)      { src = w0; off = i; }
    else if (i < (size_t)RW_FC1)  { src = w1; off = i - RW_PROJ; }
    else if (i < (size_t)RW_FC2)  { src = w2; off = i - RW_FC1; }
    else                          { src = w3; off = i - RW_FC2; }
    float4 v = *(const float4*)(src + off);
    v.x = tf32r(v.x); v.y = tf32r(v.y); v.z = tf32r(v.z); v.w = tf32r(v.w);
    *(float4*)(out + i) = v;
}

// ================= tf32 mma.sync GEMM ======================================
// Operands pre-rounded to tf32. CTA 128x128, BK=32, 8 warps (warp 64x32).
// ldmatrix fragment loads, 3-stage cp.async pipeline, 1 barrier/iter.
// MODE 0: plain; 1: 2*(acc+bias); 2: gelu(acc+bias)+tf32 round; 3: acc+bias+res
#define BKK 32
#define PAD 36
#define AS_BYTES (128 * PAD * 4)     // 18432
#define STAGE_B  (2 * AS_BYTES)      // 36864
#define GSMEM    (3 * STAGE_B)       // 110592

template <int MODE>
__global__ void __launch_bounds__(256, 2) tc_gemm(const float* __restrict__ A,
                                                  const float* __restrict__ W,
                                                  const float* __restrict__ bias,
                                                  const float* __restrict__ res,
                                                  float* __restrict__ Cout,
                                                  int M, int Nn, int K)
{
    extern __shared__ float smem[];
    const uint32_t sbase = smem_u32(smem);
    const int tid = threadIdx.x;
    const int bm = blockIdx.y, bn = blockIdx.x;

    const float* Ab = A + (size_t)bm * 128 * K;
    const float* Wb = W + (size_t)bn * 128 * K;
    const int nk = K / BKK;

    const int lrow = tid >> 3;
    const int lch  = (tid & 7) * 4;

    auto load_stage = [&](int slot, int k0) {
        const uint32_t sA = sbase + slot * STAGE_B;
        const uint32_t sB = sA + AS_BYTES;
        #pragma unroll
        for (int p = 0; p < 4; p++) {
            const int row = lrow + p * 32;
            const uint32_t off = (uint32_t)(row * PAD + lch) * 4u;
            cp16(sA + off, Ab + (size_t)row * K + k0 + lch);
            cp16(sB + off, Wb + (size_t)row * K + k0 + lch);
        }
        asm volatile("cp.async.commit_group;" ::: "memory");
    };

    load_stage(0, 0);
    load_stage(1, BKK);

    const int wid = tid >> 5, lane = tid & 31;
    const int wm = (wid >> 2) * 64;
    const int wn = (wid & 3) * 32;
    const int qr = lane >> 2, qc = lane & 3;

    // ldmatrix per-lane row addresses (bytes)
    const int l7 = lane & 7;
    const int aRow = wm + l7 + ((lane >> 3) & 1) * 8;   // + mi*16
    const int aK   = ((lane >> 4) & 1) * 4;             // + kc*8
    const uint32_t aOff = (uint32_t)(aRow * PAD + aK) * 4u;
    const int bRow = wn + l7;                           // + ni*8
    const int bK   = ((lane >> 3) & 1) * 4;             // + kc*8 (lanes 0-15 used)
    const uint32_t bOff = (uint32_t)(bRow * PAD + bK) * 4u;

    float acc[4][4][4];
    #pragma unroll
    for (int mi = 0; mi < 4; mi++)
        #pragma unroll
        for (int ni = 0; ni < 4; ni++)
            #pragma unroll
            for (int u = 0; u < 4; u++) acc[mi][ni][u] = 0.0f;

    int slot = 0, slot2 = 2;
    for (int i = 0; i < nk; i++) {
        if (i == nk - 1) asm volatile("cp.async.wait_group 0;" ::: "memory");
        else             asm volatile("cp.async.wait_group 1;" ::: "memory");
        __syncthreads();
        if (i + 2 < nk) load_stage(slot2, (i + 2) * BKK);

        const uint32_t sA = sbase + slot * STAGE_B;
        const uint32_t sB = sA + AS_BYTES;
        #pragma unroll
        for (int kc = 0; kc < 4; kc++) {
            uint32_t af[4][4], bf[4][2];
            #pragma unroll
            for (int mi = 0; mi < 4; mi++)
                ldsm_x4(af[mi], sA + aOff + (uint32_t)(mi * 16 * PAD * 4) + (uint32_t)(kc * 32));
            #pragma unroll
            for (int ni = 0; ni < 4; ni++)
                ldsm_x2(bf[ni], sB + bOff + (uint32_t)(ni * 8 * PAD * 4) + (uint32_t)(kc * 32));
            #pragma unroll
            for (int mi = 0; mi < 4; mi++)
                #pragma unroll
                for (int ni = 0; ni < 4; ni++)
                    mma_tf32(acc[mi][ni], af[mi], bf[ni]);
        }
        slot = (slot + 1 == 3) ? 0 : slot + 1;
        slot2 = (slot2 + 1 == 3) ? 0 : slot2 + 1;
    }

    #pragma unroll
    for (int mi = 0; mi < 4; mi++) {
        #pragma unroll
        for (int ni = 0; ni < 4; ni++) {
            const int col = bn * 128 + wn + ni * 8 + 2 * qc;
            #pragma unroll
            for (int half = 0; half < 2; half++) {
                const size_t row = (size_t)bm * 128 + wm + mi * 16 + qr + half * 8;
                float v0 = acc[mi][ni][half * 2 + 0];
                float v1 = acc[mi][ni][half * 2 + 1];
                if (MODE == 1) {
                    v0 = 2.0f * (v0 + bias[col]);
                    v1 = 2.0f * (v1 + bias[col + 1]);
                } else if (MODE == 2) {
                    v0 += bias[col];
                    v1 += bias[col + 1];
                    v0 = 0.5f * v0 * (1.0f + erff(v0 * 0.70710678118654752f));
                    v1 = 0.5f * v1 * (1.0f + erff(v1 * 0.70710678118654752f));
                    v0 = tf32r(v0);
                    v1 = tf32r(v1);
                } else if (MODE == 3) {
                    const float* rr = res + row * Nn + col;
                    v0 += bias[col] + rr[0];
                    v1 += bias[col + 1] + rr[1];
                }
                *(float2*)(Cout + row * Nn + col) = make_float2(v0, v1);
            }
        }
    }
}

// ---------------- fused LayerNorm (tf32-rounded output) --------------------
__global__ void __launch_bounds__(256) ln_kernel(const float* __restrict__ x,
                                                 const float* __restrict__ w,
                                                 const float* __restrict__ b,
                                                 float* __restrict__ out)
{
    __shared__ float red[8];
    const int row = blockIdx.x;
    const int t   = threadIdx.x;
    const float* xr = x + (size_t)row * C_;

    float v0 = xr[t], v1 = xr[t + 256], v2 = xr[t + 512];
    float s = v0 + v1 + v2;
    #pragma unroll
    for (int o = 16; o; o >>= 1) s += __shfl_xor_sync(0xffffffffu, s, o);
    if ((t & 31) == 0) red[t >> 5] = s;
    __syncthreads();
    float tot = red[0]+red[1]+red[2]+red[3]+red[4]+red[5]+red[6]+red[7];
    const float mu = tot * (1.0f / C_);

    float d0 = v0 - mu, d1 = v1 - mu, d2 = v2 - mu;
    float q = d0*d0 + d1*d1 + d2*d2;
    #pragma unroll
    for (int o = 16; o; o >>= 1) q += __shfl_xor_sync(0xffffffffu, q, o);
    __syncthreads();
    if ((t & 31) == 0) red[t >> 5] = q;
    __syncthreads();
    float var = (red[0]+red[1]+red[2]+red[3]+red[4]+red[5]+red[6]+red[7]) * (1.0f / C_);
    const float rstd = rsqrtf(var + 1e-5f);

    float* orow = out + (size_t)row * C_;
    orow[t]       = tf32r(d0 * rstd * w[t]       + b[t]);
    orow[t + 256] = tf32r(d1 * rstd * w[t + 256] + b[t + 256]);
    orow[t + 512] = tf32r(d2 * rstd * w[t + 512] + b[t + 512]);
}

// ================= flash attention, split-tf32 mma.sync ====================
#define AT_S 72
#define AT_Q 0
#define AT_K 9216
#define AT_V 13824
#define AT_P 18432
#define ATT_SMEM ((18432 + 9216) * 4)

__global__ void __launch_bounds__(256, 2) attn_mma(const float* __restrict__ qkv,
                                                   float* __restrict__ out)
{
    extern __shared__ float sm[];
    float* Qs = sm + AT_Q;
    float* Ks = sm + AT_K;
    float* Vs = sm + AT_V;
    float* Ps = sm + AT_P;

    const int qt = blockIdx.x;
    const int bh = blockIdx.y;
    const int h  = bh % H_;
    const int b  = bh / H_;
    const int tid = threadIdx.x;
    const int w = tid >> 5, lane = tid & 31;
    const int qr = lane >> 2, qc = lane & 3;
    const int mrow = w * 16;
    const size_t rowbase = (size_t)b * N_ + (size_t)qt * 128;

    #pragma unroll
    for (int t = 0; t < 8; t++) {
        int i = tid + t * 256;
        int row = i >> 4, c4 = (i & 15) * 4;
        float4 v = *(const float4*)(qkv + (rowbase + row) * (3 * C_) + h * D_ + c4);
        *(float4*)(Qs + row * AT_S + c4) = v;
    }
    __syncthreads();

    float m0 = -INFINITY, m1 = -INFINITY, l0 = 0.0f, l1 = 0.0f;
    float O[8][4];
    #pragma unroll
    for (int nt = 0; nt < 8; nt++)
        #pragma unroll
        for (int u = 0; u < 4; u++) O[nt][u] = 0.0f;

    for (int kt = 0; kt < 8; kt++) {
        __syncthreads();
        #pragma unroll
        for (int t = 0; t < 4; t++) {
            int i = tid + t * 256;
            int row = i >> 4, c4 = (i & 15) * 4;
            const float* src = qkv + ((size_t)b * N_ + kt * 64 + row) * (3 * C_) + C_ + h * D_ + c4;
            *(float4*)(Ks + row * AT_S + c4) = *(const float4*)src;
            *(float4*)(Vs + row * AT_S + c4) = *(const float4*)(src + C_);
        }
        __syncthreads();

        float S[8][4];
        #pragma unroll
        for (int nt = 0; nt < 8; nt++)
            #pragma unroll
            for (int u = 0; u < 4; u++) S[nt][u] = 0.0f;

        #pragma unroll
        for (int kk = 0; kk < 8; kk++) {
            const float* qb = Qs + (mrow + qr) * AT_S + kk * 8 + qc;
            uint32_t ah[4], al[4];
            split2(qb[0], ah[0], al[0]);
            split2(qb[8 * AT_S], ah[1], al[1]);
            split2(qb[4], ah[2], al[2]);
            split2(qb[8 * AT_S + 4], ah[3], al[3]);
            #pragma unroll
            for (int nt = 0; nt < 8; nt++) {
                const float* kb = Ks + (nt * 8 + qr) * AT_S + kk * 8 + qc;
                uint32_t bh2[2], bl2[2];
                split2(kb[0], bh2[0], bl2[0]);
                split2(kb[4], bh2[1], bl2[1]);
                mma_tf32(S[nt], ah, bh2);
                mma_tf32(S[nt], ah, bl2);
                mma_tf32(S[nt], al, bh2);
            }
        }

        float mt0 = -INFINITY, mt1 = -INFINITY;
        #pragma unroll
        for (int nt = 0; nt < 8; nt++) {
            #pragma unroll
            for (int u = 0; u < 4; u++) S[nt][u] *= 0.125f;
            mt0 = fmaxf(mt0, fmaxf(S[nt][0], S[nt][1]));
            mt1 = fmaxf(mt1, fmaxf(S[nt][2], S[nt][3]));
        }
        mt0 = fmaxf(mt0, __shfl_xor_sync(0xffffffffu, mt0, 1));
        mt0 = fmaxf(mt0, __shfl_xor_sync(0xffffffffu, mt0, 2));
        mt1 = fmaxf(mt1, __shfl_xor_sync(0xffffffffu, mt1, 1));
        mt1 = fmaxf(mt1, __shfl_xor_sync(0xffffffffu, mt1, 2));
        const float mn0 = fmaxf(m0, mt0), mn1 = fmaxf(m1, mt1);
        const float a0 = __expf(m0 - mn0), a1 = __expf(m1 - mn1);
        float ls0 = 0.0f, ls1 = 0.0f;
        #pragma unroll
        for (int nt = 0; nt < 8; nt++) {
            S[nt][0] = __expf(S[nt][0] - mn0);
            S[nt][1] = __expf(S[nt][1] - mn0);
            S[nt][2] = __expf(S[nt][2] - mn1);
            S[nt][3] = __expf(S[nt][3] - mn1);
            ls0 += S[nt][0] + S[nt][1];
            ls1 += S[nt][2] + S[nt][3];
        }
        ls0 += __shfl_xor_sync(0xffffffffu, ls0, 1);
        ls0 += __shfl_xor_sync(0xffffffffu, ls0, 2);
        ls1 += __shfl_xor_sync(0xffffffffu, ls1, 1);
        ls1 += __shfl_xor_sync(0xffffffffu, ls1, 2);
        l0 = l0 * a0 + ls0;
        l1 = l1 * a1 + ls1;
        m0 = mn0; m1 = mn1;
        #pragma unroll
        for (int nt = 0; nt < 8; nt++) {
            O[nt][0] *= a0; O[nt][1] *= a0;
            O[nt][2] *= a1; O[nt][3] *= a1;
        }

        #pragma unroll
        for (int nt = 0; nt < 8; nt++) {
            *(float2*)(Ps + (mrow + qr) * AT_S + nt * 8 + 2 * qc)     = make_float2(S[nt][0], S[nt][1]);
            *(float2*)(Ps + (mrow + qr + 8) * AT_S + nt * 8 + 2 * qc) = make_float2(S[nt][2], S[nt][3]);
        }
        __syncwarp();

        #pragma unroll
        for (int kk = 0; kk < 8; kk++) {
            const float* pb = Ps + (mrow + qr) * AT_S + kk * 8 + qc;
            uint32_t ph[4], pl[4];
            split2(pb[0], ph[0], pl[0]);
            split2(pb[8 * AT_S], ph[1], pl[1]);
            split2(pb[4], ph[2], pl[2]);
            split2(pb[8 * AT_S + 4], ph[3], pl[3]);
            #pragma unroll
            for (int nt = 0; nt < 8; nt++) {
                const float* vb = Vs + (kk * 8 + qc) * AT_S + nt * 8 + qr;
                uint32_t vh2[2], vl2[2];
                split2(vb[0], vh2[0], vl2[0]);
                split2(vb[4 * AT_S], vh2[1], vl2[1]);
                mma_tf32(O[nt], ph, vh2);
                mma_tf32(O[nt], ph, vl2);
                mma_tf32(O[nt], pl, vh2);
            }
        }
    }

    const float inv0 = 1.0f / l0, inv1 = 1.0f / l1;
    #pragma unroll
    for (int nt = 0; nt < 8; nt++) {
        const int col = h * D_ + nt * 8 + 2 * qc;
        const size_t r0 = rowbase + mrow + qr;
        *(float2*)(out + r0 * C_ + col) =
            make_float2(tf32r(O[nt][0] * inv0), tf32r(O[nt][1] * inv0));
        *(float2*)(out + (r0 + 8) * C_ + col) =
            make_float2(tf32r(O[nt][2] * inv1), tf32r(O[nt][3] * inv1));
    }
}

// ---------------- host launcher -------------------------------------------
extern "C" void kernel_launch(void* const* d_in, const int* in_sizes, int n_in,
                              void* d_out, int out_size)
{
    (void)in_sizes; (void)n_in; (void)out_size;
    const float* x      = (const float*)d_in[0];
    const float* ln1_w  = (const float*)d_in[1];
    const float* ln1_b  = (const float*)d_in[2];
    const float* qkv_w  = (const float*)d_in[3];
    const float* proj_w = (const float*)d_in[4];
    const float* proj_b = (const float*)d_in[5];
    const float* ln2_w  = (const float*)d_in[6];
    const float* ln2_b  = (const float*)d_in[7];
    const float* fc1_w  = (const float*)d_in[8];
    const float* fc1_b  = (const float*)d_in[9];
    const float* fc2_w  = (const float*)d_in[10];
    const float* fc2_b  = (const float*)d_in[11];
    float* out = (float*)d_out;

    float *h1, *qkvb, *attn, *x2, *ln2o, *fc1o, *rw;
    cudaGetSymbolAddress((void**)&h1,   g_h1);
    cudaGetSymbolAddress((void**)&qkvb, g_qkv);
    cudaGetSymbolAddress((void**)&attn, g_attn);
    cudaGetSymbolAddress((void**)&x2,   g_x2);
    cudaGetSymbolAddress((void**)&ln2o, g_ln2);
    cudaGetSymbolAddress((void**)&fc1o, g_fc1);
    cudaGetSymbolAddress((void**)&rw,   g_rw);

    static bool attr_done = false;
    if (!attr_done) {
        cudaFuncSetAttribute(tc_gemm<0>, cudaFuncAttributeMaxDynamicSharedMemorySize, GSMEM);
        cudaFuncSetAttribute(tc_gemm<1>, cudaFuncAttributeMaxDynamicSharedMemorySize, GSMEM);
        cudaFuncSetAttribute(tc_gemm<2>, cudaFuncAttributeMaxDynamicSharedMemorySize, GSMEM);
        cudaFuncSetAttribute(tc_gemm<3>, cudaFuncAttributeMaxDynamicSharedMemorySize, GSMEM);
        cudaFuncSetAttribute(attn_mma,   cudaFuncAttributeMaxDynamicSharedMemorySize, ATT_SMEM);
        attr_done = true;
    }

    round_all_kernel<<<(RW_TOT/4 + 255)/256, 256>>>(qkv_w, proj_w, fc1_w, fc2_w, rw);

    ln_kernel<<<M_, 256>>>(x, ln1_w, ln1_b, h1);
    tc_gemm<0><<<dim3(3*C_/128, M_/128), 256, GSMEM>>>(h1, rw + RW_QKV, nullptr, nullptr, qkvb, M_, 3*C_, C_);
    attn_mma<<<dim3(4, B_*H_), 256, ATT_SMEM>>>(qkvb, attn);
    tc_gemm<1><<<dim3(C_/128, M_/128), 256, GSMEM>>>(attn, rw + RW_PROJ, proj_b, nullptr, x2, M_, C_, C_);
    ln_kernel<<<M_, 256>>>(x2, ln2_w, ln2_b, ln2o);
    tc_gemm<2><<<dim3(HID_/128, M_/128), 256, GSMEM>>>(ln2o, rw + RW_FC1, fc1_b, nullptr, fc1o, M_, HID_, C_);
    tc_gemm<3><<<dim3(C_/128, M_/128), 256, GSMEM>>>(fc1o, rw + RW_FC2, fc2_b, x2, out, M_, C_, HID_);
}